// round 1
// baseline (speedup 1.0000x reference)
#include <cuda_runtime.h>
#include <cstdint>

// Problem constants
// x: [B=8, Ci=32, T=128, X=256, P=3] f32
// w*: [Ci=32, Co=32, 16, 16, 3] f32
// out: [8, 32, 128, 256, 3] f32
#define B_  8
#define CI_ 32
#define CO_ 32
#define T_  128
#define X_  256
#define P_  3
#define KX_ 16
#define KT_ 32
#define KP_ 2

// Scratch (device globals; allocation-free rule)
__device__ float2 g_A[B_*CI_*KX_*KP_*T_];   // [bci][kx][kp][t]      8 MB
__device__ float2 g_C[KT_*KX_*KP_*B_*CI_];  // [mode][b][ci]         2 MB
__device__ float2 g_D[KT_*KX_*KP_*B_*CO_];  // [mode][b][co]         2 MB
__device__ float2 g_H[B_*CO_*T_*KX_*KP_];   // [bco][t][kx][kp]      8 MB

__device__ __forceinline__ float2 cmulf(float2 a, float2 b) {
    return make_float2(a.x*b.x - a.y*b.y, a.x*b.y + a.y*b.x);
}

// In-register radix-2 FFT-16. SGN=-1: forward (e^{-2pi i nk/16}); SGN=+1: inverse (unscaled).
template<int SGN>
__device__ __forceinline__ void fft16(float2 v[16]) {
    float2 tmp;
#define SW_(i,j) { tmp=v[i]; v[i]=v[j]; v[j]=tmp; }
    SW_(1,8) SW_(2,4) SW_(3,12) SW_(5,10) SW_(7,14) SW_(11,13)
#undef SW_
    const float Ct[8] = {1.f, 0.92387953251f, 0.70710678119f, 0.38268343236f,
                         0.f, -0.38268343236f, -0.70710678119f, -0.92387953251f};
    const float St[8] = {0.f, 0.38268343236f, 0.70710678119f, 0.92387953251f,
                         1.f, 0.92387953251f, 0.70710678119f, 0.38268343236f};
#pragma unroll
    for (int m = 2; m <= 16; m <<= 1) {
        const int half = m >> 1;
        const int step = 16 / m;
#pragma unroll
        for (int k0 = 0; k0 < 16; k0 += m) {
#pragma unroll
            for (int j = 0; j < half; j++) {
                float2 wt = make_float2(Ct[j*step], (float)SGN * St[j*step]);
                float2 t = cmulf(v[k0+j+half], wt);
                float2 u = v[k0+j];
                v[k0+j]      = make_float2(u.x + t.x, u.y + t.y);
                v[k0+j+half] = make_float2(u.x - t.x, u.y - t.y);
            }
        }
    }
}

// ---------------------------------------------------------------------------
// K1: forward P-stage (rfft3 -> 2 modes) + pruned X-DFT (256 -> 16 modes)
// One warp per (b,ci,t) line; lane = (b_res in 0..15, kp in 0..1).
// X split: n = 16a + b_res.  X_k = sum_b w256^{bk} * FFT16_a( u_{16a+b} )[k]
// ---------------------------------------------------------------------------
__global__ void __launch_bounds__(256) k_fwd_px(const float* __restrict__ x) {
    __shared__ float2 region[8][544];   // per-line union: raw row (768 f) then transpose buf (16x33 f2)
    __shared__ float2 tw[256];          // e^{-2pi i n/256}
    __shared__ float2 outstage[8][32];

    const int tid = threadIdx.x;
    {
        float sv, cv;
        sincosf(-6.283185307179586f * (float)tid * (1.0f/256.0f), &sv, &cv);
        tw[tid] = make_float2(cv, sv);
    }
    const int bci = blockIdx.x >> 4;
    const int t0  = (blockIdx.x & 15) << 3;

    // Stage 8 rows (6144 floats) coalesced via float4
    const float4* src = (const float4*)(x + (size_t)(bci*T_ + t0) * (X_*P_));
#pragma unroll
    for (int i = 0; i < 6; i++) {
        int idx = tid + i*256;        // float4 idx 0..1535
        float4 vv = src[idx];
        int fl = idx * 4;
        int line = fl / 768, off = fl % 768;
        float* rp = (float*)region[line];
        rp[off] = vv.x; rp[off+1] = vv.y; rp[off+2] = vv.z; rp[off+3] = vv.w;
    }
    __syncthreads();

    const int w  = tid >> 5;
    const int ln = tid & 31;
    const int b_ = ln & 15;
    const int kp = ln >> 4;

    const float* rp = (const float*)region[w];
    float2 v[16];
#pragma unroll
    for (int a = 0; a < 16; a++) {
        int base = (a*16 + b_) * 3;
        float xa = rp[base], xb = rp[base+1], xc = rp[base+2];
        if (kp == 0) v[a] = make_float2(xa + xb + xc, 0.f);
        else         v[a] = make_float2(xa - 0.5f*(xb+xc), 0.8660254037844386f*(xc - xb));
    }
    __syncwarp();          // all lanes done reading raw before overwrite
    fft16<-1>(v);

    float2* trb = region[w];
#pragma unroll
    for (int k = 0; k < 16; k++) {
        float2 z = cmulf(v[k], tw[b_*k]);     // outer twiddle w256^{b*k}
        trb[b_*33 + kp*16 + k] = z;
    }
    __syncwarp();

    // reduce over b: lane -> output (ko,kpo)
    const int ko = ln & 15, kpo = ln >> 4;
    float2 acc = make_float2(0.f, 0.f);
#pragma unroll
    for (int b = 0; b < 16; b++) {
        float2 z = trb[b*33 + kpo*16 + ko];
        acc.x += z.x; acc.y += z.y;
    }
    outstage[w][ln] = acc;   // order kp*16+k
    __syncthreads();

    // coalesced write: [bci][kx][kp][t]
    const int idx = tid >> 3;      // 0..31
    const int tt  = tid & 7;
    const int k   = idx & 15, kpp = idx >> 4;
    g_A[(((size_t)bci*KX_ + k)*KP_ + kpp)*T_ + t0 + tt] = outstage[tt][kpp*16 + k];
}

// ---------------------------------------------------------------------------
// K2: forward T-DFT (128 -> 32 corner modes). 2 lines per block of 256.
// line = (bci, kx, kp).  f = kt (kt<16) or kt+96 (kt>=16).
// ---------------------------------------------------------------------------
__global__ void __launch_bounds__(256) k_fwd_t() {
    __shared__ float2 tab[128];      // e^{-2pi i n/128}
    __shared__ float2 As[2][128];
    __shared__ float2 part[2][4][32];
    const int tid = threadIdx.x;
    if (tid < 128) {
        float sv, cv;
        sincosf(-6.283185307179586f * (float)tid * (1.0f/128.0f), &sv, &cv);
        tab[tid] = make_float2(cv, sv);
    }
    const int half = tid >> 7, st = tid & 127;
    const int L = blockIdx.x*2 + half;
    As[half][st] = g_A[(size_t)L*128 + st];
    __syncthreads();

    const int out = st & 31, chunk = st >> 5;
    const int f = (out < 16) ? out : (out + 96);
    const int tstart = chunk * 32;
    float2 wv = tab[(f*tstart) & 127];
    const float2 m = tab[f];
    float2 acc = make_float2(0.f, 0.f);
#pragma unroll
    for (int i = 0; i < 32; i++) {
        float2 d = As[half][tstart + i];
        acc.x += d.x*wv.x - d.y*wv.y;
        acc.y += d.x*wv.y + d.y*wv.x;
        wv = cmulf(wv, m);
    }
    part[half][chunk][out] = acc;
    __syncthreads();
    if (st < 32) {
        float2 a0 = part[half][0][st], a1 = part[half][1][st];
        float2 a2 = part[half][2][st], a3 = part[half][3][st];
        float2 r = make_float2(a0.x+a1.x+a2.x+a3.x, a0.y+a1.y+a2.y+a3.y);
        const int bci = L >> 5, rem = L & 31;       // rem = kx*2+kp
        const int b = bci >> 5, ci = bci & 31;
        const int mode = st*32 + rem;               // (kt*16+kx)*2+kp
        g_C[(size_t)mode*256 + b*32 + ci] = r;
    }
}

// ---------------------------------------------------------------------------
// K3: per-mode complex einsum over channels: D[b,co] = sum_ci C[b,ci]*W[ci,co]
// mode = (kt,kx,kp); w1 for kt<16, w2 for kt>=16. Folds 1/(T*X).
// ---------------------------------------------------------------------------
__global__ void __launch_bounds__(256) k_einsum(const float* __restrict__ w1r, const float* __restrict__ w1i,
                                               const float* __restrict__ w2r, const float* __restrict__ w2i) {
    __shared__ float2 Cs[256];
    __shared__ float2 Ws[1024];
    const int tid = threadIdx.x;
    const int mode = blockIdx.x;
    const int kp = mode & 1, kx = (mode >> 1) & 15, kt = mode >> 5;
    Cs[tid] = g_C[(size_t)mode*256 + tid];
    const float* wr; const float* wi; int ktw;
    if (kt < 16) { wr = w1r; wi = w1i; ktw = kt; }
    else         { wr = w2r; wi = w2i; ktw = kt - 16; }
#pragma unroll
    for (int i = 0; i < 4; i++) {
        int e = tid + i*256;                           // e = ci*32+co
        int base = e*768 + (ktw*16 + kx)*3 + kp;
        Ws[e] = make_float2(wr[base], wi[base]);
    }
    __syncthreads();
    const int b = tid >> 5, co = tid & 31;
    float2 acc = make_float2(0.f, 0.f);
#pragma unroll
    for (int ci = 0; ci < 32; ci++) {
        float2 c = Cs[b*32 + ci];
        float2 wv = Ws[ci*32 + co];
        acc.x += c.x*wv.x - c.y*wv.y;
        acc.y += c.x*wv.y + c.y*wv.x;
    }
    const float INV_TX = 1.0f / (128.0f * 256.0f);
    g_D[(size_t)mode*256 + tid] = make_float2(acc.x*INV_TX, acc.y*INV_TX);
}

// ---------------------------------------------------------------------------
// K4: inverse T (32 corner modes -> 128 t). 2 lines per block of 256.
// h_t = sum_{j<16} D_j e^{+2pi i j t/128} + sum_{j=16..31} D_j e^{+2pi i (j+96) t/128}
// ---------------------------------------------------------------------------
__global__ void __launch_bounds__(256) k_inv_t() {
    __shared__ float2 tab[128];      // e^{+2pi i n/128}
    __shared__ float2 Dl[2][32];
    const int tid = threadIdx.x;
    if (tid < 128) {
        float sv, cv;
        sincosf(6.283185307179586f * (float)tid * (1.0f/128.0f), &sv, &cv);
        tab[tid] = make_float2(cv, sv);
    }
    const int half = tid >> 7, st = tid & 127;
    const int L = blockIdx.x*2 + half;
    const int bco = L >> 5, rem = L & 31;
    const int b = bco >> 5, co = bco & 31;
    if (st < 32) {
        int mode = st*32 + rem;
        Dl[half][st] = g_D[(size_t)mode*256 + b*32 + co];
    }
    __syncthreads();
    const int t = st;
    const float2 m = tab[t];
    float2 wv = make_float2(1.f, 0.f);
    float2 acc = make_float2(0.f, 0.f);
#pragma unroll
    for (int j = 0; j < 16; j++) {
        float2 d = Dl[half][j];
        acc.x += d.x*wv.x - d.y*wv.y;
        acc.y += d.x*wv.y + d.y*wv.x;
        wv = cmulf(wv, m);
    }
    wv = tab[(112*t) & 127];
#pragma unroll
    for (int j = 16; j < 32; j++) {
        float2 d = Dl[half][j];
        acc.x += d.x*wv.x - d.y*wv.y;
        acc.y += d.x*wv.y + d.y*wv.x;
        wv = cmulf(wv, m);
    }
    g_H[((size_t)bco*T_ + t)*32 + rem] = acc;
}

// ---------------------------------------------------------------------------
// K5: inverse X (16 modes -> 256 x, split x=b+16a: scale by w256^{kb}, iFFT16)
//     + irfft over P (2 modes -> 3 points) fused into the store.
// One warp per (b,co,t) line; 8 lines per block.
// ---------------------------------------------------------------------------
__global__ void __launch_bounds__(256) k_inv_xp(float* __restrict__ out) {
    __shared__ float2 tw[256];       // e^{+2pi i n/256}
    __shared__ float2 Hs[8][32];
    __shared__ float2 gbuf[8][2][256];
    const int tid = threadIdx.x;
    {
        float sv, cv;
        sincosf(6.283185307179586f * (float)tid * (1.0f/256.0f), &sv, &cv);
        tw[tid] = make_float2(cv, sv);
    }
    const int bco = blockIdx.x >> 4;
    const int t0  = (blockIdx.x & 15) << 3;
    Hs[tid>>5][tid&31] = g_H[((size_t)bco*T_ + t0 + (tid>>5))*32 + (tid&31)];
    __syncthreads();

    const int w  = tid >> 5;
    const int ln = tid & 31;
    const int b_ = ln & 15;
    const int kp = ln >> 4;

    float2 v[16];
#pragma unroll
    for (int k = 0; k < 16; k++)
        v[k] = cmulf(Hs[w][k*2 + kp], tw[k*b_]);   // w256^{k*b}
    fft16<1>(v);                                    // -> g at x = b_ + 16a
#pragma unroll
    for (int a = 0; a < 16; a++)
        gbuf[w][kp][b_ + a*16] = v[a];
    __syncwarp();

    const int t = t0 + w;
    float* obase = out + ((size_t)bco*T_ + t) * (X_*P_);
    const float TH = 1.0f / 3.0f;
    const float SQ3 = 1.7320508075688772f;
#pragma unroll
    for (int i = 0; i < 8; i++) {
        int xx = ln + i*32;
        float2 g0 = gbuf[w][0][xx];
        float2 g1 = gbuf[w][1][xx];
        float r = g0.x;
        obase[xx*3 + 0] = (r + 2.f*g1.x) * TH;
        obase[xx*3 + 1] = (r - g1.x - SQ3*g1.y) * TH;
        obase[xx*3 + 2] = (r - g1.x + SQ3*g1.y) * TH;
    }
}

extern "C" void kernel_launch(void* const* d_in, const int* in_sizes, int n_in,
                              void* d_out, int out_size) {
    const float* x   = (const float*)d_in[0];
    const float* w1r = (const float*)d_in[1];
    const float* w1i = (const float*)d_in[2];
    const float* w2r = (const float*)d_in[3];
    const float* w2i = (const float*)d_in[4];
    float* out = (float*)d_out;

    k_fwd_px<<<4096, 256>>>(x);     // B*Ci*T/8 blocks
    k_fwd_t <<<4096, 256>>>();      // 8192 lines / 2
    k_einsum<<<1024, 256>>>(w1r, w1i, w2r, w2i);
    k_inv_t <<<4096, 256>>>();      // 8192 lines / 2
    k_inv_xp<<<4096, 256>>>(out);   // B*Co*T/8 blocks
}

// round 2
// speedup vs baseline: 1.1230x; 1.1230x over previous
#include <cuda_runtime.h>
#include <cstdint>

// Problem constants
// x: [B=8, Ci=32, T=128, X=256, P=3] f32
// w*: [Ci=32, Co=32, 16, 16, 3] f32
// out: [8, 32, 128, 256, 3] f32
#define B_  8
#define CI_ 32
#define CO_ 32
#define T_  128
#define X_  256
#define P_  3
#define KX_ 16
#define KT_ 32
#define KP_ 2

// Scratch (device globals; allocation-free rule)
__device__ float2 g_A[B_*CI_*KX_*KP_*T_];   // [bci][kx][kp][t]      8 MB
__device__ float2 g_C[KT_*KX_*KP_*B_*CI_];  // [mode][bci]           2 MB
__device__ float2 g_D[B_*CO_*KT_*KX_*KP_];  // [bco][mode]           2 MB (transposed!)
__device__ float2 g_H[B_*CO_*T_*KX_*KP_];   // [bco][t][rem]         8 MB

__device__ __forceinline__ float2 cmulf(float2 a, float2 b) {
    return make_float2(a.x*b.x - a.y*b.y, a.x*b.y + a.y*b.x);
}

// In-register radix-2 FFT-16. SGN=-1: forward (e^{-2pi i nk/16}); SGN=+1: inverse (unscaled).
template<int SGN>
__device__ __forceinline__ void fft16(float2 v[16]) {
    float2 tmp;
#define SW_(i,j) { tmp=v[i]; v[i]=v[j]; v[j]=tmp; }
    SW_(1,8) SW_(2,4) SW_(3,12) SW_(5,10) SW_(7,14) SW_(11,13)
#undef SW_
    const float Ct[8] = {1.f, 0.92387953251f, 0.70710678119f, 0.38268343236f,
                         0.f, -0.38268343236f, -0.70710678119f, -0.92387953251f};
    const float St[8] = {0.f, 0.38268343236f, 0.70710678119f, 0.92387953251f,
                         1.f, 0.92387953251f, 0.70710678119f, 0.38268343236f};
#pragma unroll
    for (int m = 2; m <= 16; m <<= 1) {
        const int half = m >> 1;
        const int step = 16 / m;
#pragma unroll
        for (int k0 = 0; k0 < 16; k0 += m) {
#pragma unroll
            for (int j = 0; j < half; j++) {
                float2 wt = make_float2(Ct[j*step], (float)SGN * St[j*step]);
                float2 t = cmulf(v[k0+j+half], wt);
                float2 u = v[k0+j];
                v[k0+j]      = make_float2(u.x + t.x, u.y + t.y);
                v[k0+j+half] = make_float2(u.x - t.x, u.y - t.y);
            }
        }
    }
}

// ---------------------------------------------------------------------------
// K1: forward P-stage (rfft3 -> 2 modes) + pruned X-DFT (256 -> 16 modes)
// One warp per (b,ci,t) line; lane = (b_res in 0..15, kp in 0..1).
// X split: n = 16a + b_res.  X_k = sum_b w256^{bk} * FFT16_a( u_{16a+b} )[k]
// ---------------------------------------------------------------------------
__global__ void __launch_bounds__(256) k_fwd_px(const float* __restrict__ x) {
    __shared__ float2 region[8][544];   // per-line union: raw row (768 f) then transpose buf (16x33 f2)
    __shared__ float2 tw[256];          // e^{-2pi i n/256}
    __shared__ float2 outstage[8][32];

    const int tid = threadIdx.x;
    {
        float sv, cv;
        sincosf(-6.283185307179586f * (float)tid * (1.0f/256.0f), &sv, &cv);
        tw[tid] = make_float2(cv, sv);
    }
    const int bci = blockIdx.x >> 4;
    const int t0  = (blockIdx.x & 15) << 3;

    // Stage 8 rows (6144 floats) coalesced via float4
    const float4* src = (const float4*)(x + (size_t)(bci*T_ + t0) * (X_*P_));
#pragma unroll
    for (int i = 0; i < 6; i++) {
        int idx = tid + i*256;        // float4 idx 0..1535
        float4 vv = src[idx];
        int fl = idx * 4;
        int line = fl / 768, off = fl % 768;
        *(float4*)((float*)region + line*1088 + off) = vv;
    }
    __syncthreads();

    const int w  = tid >> 5;
    const int ln = tid & 31;
    const int b_ = ln & 15;
    const int kp = ln >> 4;

    const float* rp = (const float*)region[w];
    float2 v[16];
#pragma unroll
    for (int a = 0; a < 16; a++) {
        int base = (a*16 + b_) * 3;
        float xa = rp[base], xb = rp[base+1], xc = rp[base+2];
        if (kp == 0) v[a] = make_float2(xa + xb + xc, 0.f);
        else         v[a] = make_float2(xa - 0.5f*(xb+xc), 0.8660254037844386f*(xc - xb));
    }
    __syncwarp();          // all lanes done reading raw before overwrite
    fft16<-1>(v);

    float2* trb = region[w];
#pragma unroll
    for (int k = 0; k < 16; k++) {
        float2 z = cmulf(v[k], tw[b_*k]);     // outer twiddle w256^{b*k}
        trb[b_*33 + kp*16 + k] = z;
    }
    __syncwarp();

    // reduce over b: lane -> output (ko,kpo)
    const int ko = ln & 15, kpo = ln >> 4;
    float2 acc = make_float2(0.f, 0.f);
#pragma unroll
    for (int b = 0; b < 16; b++) {
        float2 z = trb[b*33 + kpo*16 + ko];
        acc.x += z.x; acc.y += z.y;
    }
    outstage[w][ln] = acc;   // order kp*16+k
    __syncthreads();

    // coalesced write: [bci][kx][kp][t]
    const int idx = tid >> 3;      // 0..31
    const int tt  = tid & 7;
    const int k   = idx & 15, kpp = idx >> 4;
    g_A[(((size_t)bci*KX_ + k)*KP_ + kpp)*T_ + t0 + tt] = outstage[tt][kpp*16 + k];
}

// ---------------------------------------------------------------------------
// K2: forward T-DFT (128 -> 32 corner modes) via radix split T = 8a + b.
// C_f = sum_{b<8} w128^{bf} * FFT16_a(A_{8a+b})[f mod 16]
// Block = one bci (32 lines: rem = kx*2+kp). Warp = 4 lines; lane = (l, b).
// ---------------------------------------------------------------------------
__global__ void __launch_bounds__(256) k_fwd_t() {
    __shared__ float2 tab[128];       // e^{-2pi i n/128}
    __shared__ float2 reg[8][544];    // per-warp union: As[4][136] then fb[32][17]
    const int tid = threadIdx.x;
    if (tid < 128) {
        float sv, cv;
        sincosf(-6.283185307179586f * (float)tid * (1.0f/128.0f), &sv, &cv);
        tab[tid] = make_float2(cv, sv);
    }
    const int bci = blockIdx.x;       // 256 blocks

    // coalesced load of 32 lines x 128 f2 (contiguous 32KB)
    const float4* src = (const float4*)(g_A + (size_t)bci*4096);
#pragma unroll
    for (int i = 0; i < 8; i++) {
        int idx = tid + i*256;        // f4 idx 0..2047
        float4 vv = src[idx];
        int f2i = idx*2;
        int line = f2i >> 7, t = f2i & 127;
        *(float4*)&reg[line>>2][(line&3)*136 + t] = vv;
    }
    __syncthreads();

    const int w = tid >> 5, ln = tid & 31;
    const int l = ln >> 3, b = ln & 7;
    float2* R = reg[w];

    float2 v[16];
#pragma unroll
    for (int a = 0; a < 16; a++) v[a] = R[l*136 + a*8 + b];
    __syncwarp();
    fft16<-1>(v);
    // fb[lane][k]
#pragma unroll
    for (int k = 0; k < 16; k++) R[ln*17 + k] = v[k];
    __syncwarp();

    // combine: lane = output mode o (kt); f = o or o+96
    const int o  = ln;
    const int f  = (o < 16) ? o : (o + 96);
    const int km = o & 15;
    float2 acc[4];
#pragma unroll
    for (int q = 0; q < 4; q++) acc[q] = make_float2(0.f, 0.f);
#pragma unroll
    for (int bb = 0; bb < 8; bb++) {
        float2 twv = tab[(bb*f) & 127];
#pragma unroll
        for (int q = 0; q < 4; q++) {
            float2 z = R[(q*8 + bb)*17 + km];
            acc[q].x += z.x*twv.x - z.y*twv.y;
            acc[q].y += z.x*twv.y + z.y*twv.x;
        }
    }
    // scatter store: mode = o*32 + rem, element bci
#pragma unroll
    for (int q = 0; q < 4; q++) {
        int rem = w*4 + q;
        g_C[((size_t)o*32 + rem)*256 + bci] = acc[q];
    }
}

// ---------------------------------------------------------------------------
// K3: per-mode complex einsum over channels: D[b,co] = sum_ci C[b,ci]*W[ci,co]
// mode = (kt,kx,kp); w1 for kt<16, w2 for kt>=16. Folds 1/(T*X).
// Stores TRANSPOSED: g_D[bco][mode] so K4 loads coalesced.
// ---------------------------------------------------------------------------
__global__ void __launch_bounds__(256) k_einsum(const float* __restrict__ w1r, const float* __restrict__ w1i,
                                               const float* __restrict__ w2r, const float* __restrict__ w2i) {
    __shared__ float2 Cs[256];
    __shared__ float2 Ws[1024];
    const int tid = threadIdx.x;
    const int mode = blockIdx.x;
    const int kp = mode & 1, kx = (mode >> 1) & 15, kt = mode >> 5;
    Cs[tid] = g_C[(size_t)mode*256 + tid];
    const float* wr; const float* wi; int ktw;
    if (kt < 16) { wr = w1r; wi = w1i; ktw = kt; }
    else         { wr = w2r; wi = w2i; ktw = kt - 16; }
#pragma unroll
    for (int i = 0; i < 4; i++) {
        int e = tid + i*256;                           // e = ci*32+co
        int base = e*768 + (ktw*16 + kx)*3 + kp;
        Ws[e] = make_float2(wr[base], wi[base]);
    }
    __syncthreads();
    const int b = tid >> 5, co = tid & 31;
    float2 acc = make_float2(0.f, 0.f);
#pragma unroll
    for (int ci = 0; ci < 32; ci++) {
        float2 c = Cs[b*32 + ci];
        float2 wv = Ws[ci*32 + co];
        acc.x += c.x*wv.x - c.y*wv.y;
        acc.y += c.x*wv.y + c.y*wv.x;
    }
    const float INV_TX = 1.0f / (128.0f * 256.0f);
    g_D[(size_t)tid*1024 + mode] = make_float2(acc.x*INV_TX, acc.y*INV_TX);
}

// ---------------------------------------------------------------------------
// K4: inverse T (32 corner modes -> 128 t) via radix split t = 8a + b.
// Pair modes by residue r = f mod 16 (f=r and f=r+112):
//   S_b[r] = D_r w128^{br} + D_{r+16} w128^{b(r+112)};  H_{8a+b} = iFFT16(S_b)[a]
// Block = one bco (32 lines). Warp = 4 lines; lane = (l, b).
// ---------------------------------------------------------------------------
__global__ void __launch_bounds__(256) k_inv_t() {
    __shared__ float2 tab[128];       // e^{+2pi i n/128}
    __shared__ float2 Ds[32][33];     // [rem][j]
    __shared__ float2 Hs[128][33];    // [t][rem]
    const int tid = threadIdx.x;
    if (tid < 128) {
        float sv, cv;
        sincosf(6.283185307179586f * (float)tid * (1.0f/128.0f), &sv, &cv);
        tab[tid] = make_float2(cv, sv);
    }
    const int bco = blockIdx.x;       // 256 blocks

    const float2* src = g_D + (size_t)bco*1024;   // [mode = j*32+rem]
#pragma unroll
    for (int i = 0; i < 4; i++) {
        int idx = tid + i*256;
        Ds[idx & 31][idx >> 5] = src[idx];
    }
    __syncthreads();

    const int w = tid >> 5, ln = tid & 31;
    const int l = ln >> 3, b = ln & 7;
    const int rem = w*4 + l;

    float2 S[16];
#pragma unroll
    for (int r = 0; r < 16; r++) {
        float2 d0 = Ds[rem][r];
        float2 d1 = Ds[rem][r+16];
        float2 t0 = tab[(b*r) & 127];
        float2 t1 = tab[(b*(r+112)) & 127];
        S[r].x = d0.x*t0.x - d0.y*t0.y + d1.x*t1.x - d1.y*t1.y;
        S[r].y = d0.x*t0.y + d0.y*t0.x + d1.x*t1.y + d1.y*t1.x;
    }
    fft16<1>(S);                      // S[a] = H_{8a+b}
#pragma unroll
    for (int a = 0; a < 16; a++) Hs[a*8 + b][rem] = S[a];
    __syncthreads();

    // coalesced float4 write: g_H[bco][t][rem]
    float4* dst = (float4*)(g_H + (size_t)bco*4096);
#pragma unroll
    for (int i = 0; i < 8; i++) {
        int idx = tid + i*256;        // f4 idx; f2 = 2*idx
        int t = (2*idx) >> 5, r2 = (2*idx) & 31;
        float2 a = Hs[t][r2], bb = Hs[t][r2+1];
        dst[idx] = make_float4(a.x, a.y, bb.x, bb.y);
    }
}

// ---------------------------------------------------------------------------
// K5: inverse X (16 modes -> 256 x, split x=b+16a: scale by w256^{kb}, iFFT16)
//     + irfft over P (2 modes -> 3 points), staged via permuted shared layout
//     so each lane emits 6 float4 (24 contiguous floats).
// perm(x) = (x>>3) + (x&7)*33  (bijective into [0,264))
// ---------------------------------------------------------------------------
__global__ void __launch_bounds__(256) k_inv_xp(float* __restrict__ out) {
    __shared__ float2 tw[256];        // e^{+2pi i n/256}
    __shared__ float2 Hsm[8][32];
    __shared__ float2 gb[8][2][264];
    const int tid = threadIdx.x;
    {
        float sv, cv;
        sincosf(6.283185307179586f * (float)tid * (1.0f/256.0f), &sv, &cv);
        tw[tid] = make_float2(cv, sv);
    }
    const int bco = blockIdx.x >> 4;
    const int t0  = (blockIdx.x & 15) << 3;
    Hsm[tid>>5][tid&31] = g_H[((size_t)bco*T_ + t0 + (tid>>5))*32 + (tid&31)];
    __syncthreads();

    const int w  = tid >> 5;
    const int ln = tid & 31;
    const int b_ = ln & 15;
    const int kp = ln >> 4;

    float2 v[16];
#pragma unroll
    for (int k = 0; k < 16; k++)
        v[k] = cmulf(Hsm[w][k*2 + kp], tw[k*b_]);   // w256^{k*b}
    fft16<1>(v);                                    // -> g at x = b_ + 16a
    const int pbase = (b_ >> 3) + (b_ & 7)*33;
#pragma unroll
    for (int a = 0; a < 16; a++)
        gb[w][kp][pbase + 2*a] = v[a];
    __syncwarp();

    // lane handles x in [8*ln, 8*ln+8): perm(8ln+j) = ln + 33j (conflict-free)
    float f[24];
    const float TH = 1.0f / 3.0f;
    const float SQ3 = 1.7320508075688772f;
#pragma unroll
    for (int j = 0; j < 8; j++) {
        float2 g0 = gb[w][0][ln + 33*j];
        float2 g1 = gb[w][1][ln + 33*j];
        float r = g0.x;
        f[3*j+0] = (r + 2.f*g1.x) * TH;
        f[3*j+1] = (r - g1.x - SQ3*g1.y) * TH;
        f[3*j+2] = (r - g1.x + SQ3*g1.y) * TH;
    }
    float4* op = (float4*)(out + ((size_t)bco*T_ + t0 + w)*768 + 24*ln);
#pragma unroll
    for (int q = 0; q < 6; q++)
        op[q] = make_float4(f[4*q], f[4*q+1], f[4*q+2], f[4*q+3]);
}

extern "C" void kernel_launch(void* const* d_in, const int* in_sizes, int n_in,
                              void* d_out, int out_size) {
    const float* x   = (const float*)d_in[0];
    const float* w1r = (const float*)d_in[1];
    const float* w1i = (const float*)d_in[2];
    const float* w2r = (const float*)d_in[3];
    const float* w2i = (const float*)d_in[4];
    float* out = (float*)d_out;

    k_fwd_px<<<4096, 256>>>(x);     // B*Ci*T/8 blocks
    k_fwd_t <<<256, 256>>>();       // one bci per block
    k_einsum<<<1024, 256>>>(w1r, w1i, w2r, w2i);
    k_inv_t <<<256, 256>>>();       // one bco per block
    k_inv_xp<<<4096, 256>>>(out);   // B*Co*T/8 blocks
}

// round 4
// speedup vs baseline: 1.1461x; 1.0206x over previous
#include <cuda_runtime.h>
#include <cstdint>

// x: [B=8, Ci=32, T=128, X=256, P=3] f32
// w*: [Ci=32, Co=32, 16, 16, 3] f32
// out: [8, 32, 128, 256, 3] f32
#define B_  8
#define CI_ 32
#define CO_ 32
#define T_  128
#define X_  256
#define P_  3
#define KX_ 16
#define KT_ 32
#define KP_ 2

__device__ float2 g_A[B_*CI_*KX_*KP_*T_];   // [bci][kx][kp][t]
__device__ float2 g_C[KT_*KX_*KP_*B_*CI_];  // [mode][bci]
__device__ float2 g_D[B_*CO_*KT_*KX_*KP_];  // [bco][mode]
__device__ float2 g_H[B_*CO_*T_*KX_*KP_];   // [bco][t][rem]

__device__ __forceinline__ float2 cmulf(float2 a, float2 b) {
    return make_float2(a.x*b.x - a.y*b.y, a.x*b.y + a.y*b.x);
}

// In-register radix-2 FFT-16. SGN=-1: forward; SGN=+1: inverse (unscaled).
template<int SGN>
__device__ __forceinline__ void fft16(float2 v[16]) {
    float2 tmp;
#define SW_(i,j) { tmp=v[i]; v[i]=v[j]; v[j]=tmp; }
    SW_(1,8) SW_(2,4) SW_(3,12) SW_(5,10) SW_(7,14) SW_(11,13)
#undef SW_
    const float Ct[8] = {1.f, 0.92387953251f, 0.70710678119f, 0.38268343236f,
                         0.f, -0.38268343236f, -0.70710678119f, -0.92387953251f};
    const float St[8] = {0.f, 0.38268343236f, 0.70710678119f, 0.92387953251f,
                         1.f, 0.92387953251f, 0.70710678119f, 0.38268343236f};
#pragma unroll
    for (int m = 2; m <= 16; m <<= 1) {
        const int half = m >> 1;
        const int step = 16 / m;
#pragma unroll
        for (int k0 = 0; k0 < 16; k0 += m) {
#pragma unroll
            for (int j = 0; j < half; j++) {
                float2 wt = make_float2(Ct[j*step], (float)SGN * St[j*step]);
                float2 t = cmulf(v[k0+j+half], wt);
                float2 u = v[k0+j];
                v[k0+j]      = make_float2(u.x + t.x, u.y + t.y);
                v[k0+j+half] = make_float2(u.x - t.x, u.y - t.y);
            }
        }
    }
}

// ---------------------------------------------------------------------------
// K1: forward P-stage (rfft3 -> 2 modes) + pruned X-DFT (256 -> 16 modes)
// ---------------------------------------------------------------------------
__global__ void __launch_bounds__(256) k_fwd_px(const float* __restrict__ x) {
    __shared__ float2 region[8][544];
    __shared__ float2 tw[256];          // e^{-2pi i n/256}
    __shared__ float2 outstage[8][32];

    const int tid = threadIdx.x;
    {
        float sv, cv;
        __sincosf(-6.283185307179586f * (float)tid * (1.0f/256.0f), &sv, &cv);
        tw[tid] = make_float2(cv, sv);
    }
    const int bci = blockIdx.x >> 4;
    const int t0  = (blockIdx.x & 15) << 3;

    const float4* src = (const float4*)(x + (size_t)(bci*T_ + t0) * (X_*P_));
#pragma unroll
    for (int i = 0; i < 6; i++) {
        int idx = tid + i*256;
        float4 vv = src[idx];
        int fl = idx * 4;
        int line = fl / 768, off = fl % 768;
        *(float4*)((float*)region + line*1088 + off) = vv;
    }
    __syncthreads();

    const int w  = tid >> 5;
    const int ln = tid & 31;
    const int b_ = ln & 15;
    const int kp = ln >> 4;

    const float* rp = (const float*)region[w];
    float2 v[16];
#pragma unroll
    for (int a = 0; a < 16; a++) {
        int base = (a*16 + b_) * 3;
        float xa = rp[base], xb = rp[base+1], xc = rp[base+2];
        if (kp == 0) v[a] = make_float2(xa + xb + xc, 0.f);
        else         v[a] = make_float2(xa - 0.5f*(xb+xc), 0.8660254037844386f*(xc - xb));
    }
    __syncwarp();
    fft16<-1>(v);

    float2* trb = region[w];
#pragma unroll
    for (int k = 0; k < 16; k++) {
        float2 z = cmulf(v[k], tw[b_*k]);
        trb[b_*33 + kp*16 + k] = z;
    }
    __syncwarp();

    const int ko = ln & 15, kpo = ln >> 4;
    float2 acc = make_float2(0.f, 0.f);
#pragma unroll
    for (int b = 0; b < 16; b++) {
        float2 z = trb[b*33 + kpo*16 + ko];
        acc.x += z.x; acc.y += z.y;
    }
    outstage[w][ln] = acc;
    __syncthreads();

    const int idx = tid >> 3;
    const int tt  = tid & 7;
    const int k   = idx & 15, kpp = idx >> 4;
    g_A[(((size_t)bci*KX_ + k)*KP_ + kpp)*T_ + t0 + tt] = outstage[tt][kpp*16 + k];
}

// ---------------------------------------------------------------------------
// K2: forward T-DFT (128 -> 32 corner modes), radix split T = 8a + b.
// Block = half a bci (16 lines), 128 threads, grid 512.
// ---------------------------------------------------------------------------
__global__ void __launch_bounds__(128) k_fwd_t() {
    __shared__ float2 tab[128];       // e^{-2pi i n/128}
    __shared__ float2 reg[4][544];    // per-warp: As[4][136] then fb[32][17]
    const int tid = threadIdx.x;
    {
        float sv, cv;
        __sincosf(-6.283185307179586f * (float)tid * (1.0f/128.0f), &sv, &cv);
        tab[tid] = make_float2(cv, sv);
    }
    const int bci = blockIdx.x >> 1;
    const int h   = blockIdx.x & 1;

    // 16 contiguous lines x 128 f2 = 16KB
    const float4* src = (const float4*)(g_A + ((size_t)bci*32 + h*16)*128);
#pragma unroll
    for (int i = 0; i < 8; i++) {
        int idx = tid + i*128;        // f4 idx 0..1023
        float4 vv = src[idx];
        int f2i = idx*2;
        int line = f2i >> 7, t = f2i & 127;
        *(float4*)&reg[line>>2][(line&3)*136 + t] = vv;
    }
    __syncthreads();

    const int w = tid >> 5, ln = tid & 31;
    const int l = ln >> 3, b = ln & 7;
    float2* R = reg[w];

    float2 v[16];
#pragma unroll
    for (int a = 0; a < 16; a++) v[a] = R[l*136 + a*8 + b];
    __syncwarp();
    fft16<-1>(v);
#pragma unroll
    for (int k = 0; k < 16; k++) R[ln*17 + k] = v[k];
    __syncwarp();

    const int o  = ln;
    const int f  = (o < 16) ? o : (o + 96);
    const int km = o & 15;
    float2 acc[4];
#pragma unroll
    for (int q = 0; q < 4; q++) acc[q] = make_float2(0.f, 0.f);
#pragma unroll
    for (int bb = 0; bb < 8; bb++) {
        float2 twv = tab[(bb*f) & 127];
#pragma unroll
        for (int q = 0; q < 4; q++) {
            float2 z = R[(q*8 + bb)*17 + km];
            acc[q].x += z.x*twv.x - z.y*twv.y;
            acc[q].y += z.x*twv.y + z.y*twv.x;
        }
    }
#pragma unroll
    for (int q = 0; q < 4; q++) {
        int rem = h*16 + w*4 + q;
        g_C[((size_t)o*32 + rem)*256 + bci] = acc[q];
    }
}

// ---------------------------------------------------------------------------
// K3: per-mode complex einsum: D[b,co] = sum_ci C[b,ci]*W[ci,co]; folds 1/(T*X)
// Stores transposed: g_D[bco][mode].
// ---------------------------------------------------------------------------
__global__ void __launch_bounds__(256) k_einsum(const float* __restrict__ w1r, const float* __restrict__ w1i,
                                               const float* __restrict__ w2r, const float* __restrict__ w2i) {
    __shared__ float2 Cs[256];
    __shared__ float2 Ws[1024];
    const int tid = threadIdx.x;
    const int mode = blockIdx.x;
    const int kp = mode & 1, kx = (mode >> 1) & 15, kt = mode >> 5;
    Cs[tid] = g_C[(size_t)mode*256 + tid];
    const float* wr; const float* wi; int ktw;
    if (kt < 16) { wr = w1r; wi = w1i; ktw = kt; }
    else         { wr = w2r; wi = w2i; ktw = kt - 16; }
#pragma unroll
    for (int i = 0; i < 4; i++) {
        int e = tid + i*256;
        int base = e*768 + (ktw*16 + kx)*3 + kp;
        Ws[e] = make_float2(wr[base], wi[base]);
    }
    __syncthreads();
    const int b = tid >> 5, co = tid & 31;
    float2 acc = make_float2(0.f, 0.f);
#pragma unroll
    for (int ci = 0; ci < 32; ci++) {
        float2 c = Cs[b*32 + ci];
        float2 wv = Ws[ci*32 + co];
        acc.x += c.x*wv.x - c.y*wv.y;
        acc.y += c.x*wv.y + c.y*wv.x;
    }
    const float INV_TX = 1.0f / (128.0f * 256.0f);
    g_D[(size_t)tid*1024 + mode] = make_float2(acc.x*INV_TX, acc.y*INV_TX);
}

// ---------------------------------------------------------------------------
// K4: inverse T (32 corner modes -> 128 t), radix split t = 8a + b.
// Block = half a bco (16 rem lines), 128 threads, grid 512.
// ---------------------------------------------------------------------------
__global__ void __launch_bounds__(128) k_inv_t() {
    __shared__ float2 tab[128];       // e^{+2pi i n/128}
    __shared__ float2 Ds[16][33];     // [rem][j]
    __shared__ float2 Hs[128][17];    // [t][rem]
    const int tid = threadIdx.x;
    {
        float sv, cv;
        __sincosf(6.283185307179586f * (float)tid * (1.0f/128.0f), &sv, &cv);
        tab[tid] = make_float2(cv, sv);
    }
    const int bco = blockIdx.x >> 1;
    const int h   = blockIdx.x & 1;

    const float2* src = g_D + (size_t)bco*1024;
#pragma unroll
    for (int i = 0; i < 4; i++) {
        int idx = tid + i*128;        // 0..511
        int j = idx >> 4, r = idx & 15;
        Ds[r][j] = src[j*32 + h*16 + r];
    }
    __syncthreads();

    const int w = tid >> 5, ln = tid & 31;
    const int l = ln >> 3, b = ln & 7;
    const int rem = w*4 + l;          // local 0..15

    float2 S[16];
#pragma unroll
    for (int r = 0; r < 16; r++) {
        float2 d0 = Ds[rem][r];
        float2 d1 = Ds[rem][r+16];
        float2 t0 = tab[(b*r) & 127];
        float2 t1 = tab[(b*(r+112)) & 127];
        S[r].x = d0.x*t0.x - d0.y*t0.y + d1.x*t1.x - d1.y*t1.y;
        S[r].y = d0.x*t0.y + d0.y*t0.x + d1.x*t1.y + d1.y*t1.x;
    }
    fft16<1>(S);                      // S[a] = H_{8a+b}
#pragma unroll
    for (int a = 0; a < 16; a++) Hs[a*8 + b][rem] = S[a];
    __syncthreads();

    // coalesced write: 128 t x 8 f4 (this block's rem half) = 1024 f4
    float4* dst = (float4*)(g_H + (size_t)bco*4096);
#pragma unroll
    for (int i = 0; i < 8; i++) {
        int idx = tid + i*128;        // 0..1023
        int t = idx >> 3, q = idx & 7;
        float2 a0 = Hs[t][q*2], a1 = Hs[t][q*2 + 1];
        dst[t*16 + h*8 + q] = make_float4(a0.x, a0.y, a1.x, a1.y);
    }
}

// ---------------------------------------------------------------------------
// K5: inverse X (16 modes -> 256 x) + irfft over P, permuted store staging.
// ---------------------------------------------------------------------------
__global__ void __launch_bounds__(256) k_inv_xp(float* __restrict__ out) {
    __shared__ float2 tw[256];        // e^{+2pi i n/256}
    __shared__ float2 Hsm[8][32];
    __shared__ float2 gb[8][2][264];
    const int tid = threadIdx.x;
    {
        float sv, cv;
        __sincosf(6.283185307179586f * (float)tid * (1.0f/256.0f), &sv, &cv);
        tw[tid] = make_float2(cv, sv);
    }
    const int bco = blockIdx.x >> 4;
    const int t0  = (blockIdx.x & 15) << 3;
    Hsm[tid>>5][tid&31] = g_H[((size_t)bco*T_ + t0 + (tid>>5))*32 + (tid&31)];
    __syncthreads();

    const int w  = tid >> 5;
    const int ln = tid & 31;
    const int b_ = ln & 15;
    const int kp = ln >> 4;

    float2 v[16];
#pragma unroll
    for (int k = 0; k < 16; k++)
        v[k] = cmulf(Hsm[w][k*2 + kp], tw[k*b_]);
    fft16<1>(v);
    const int pbase = (b_ >> 3) + (b_ & 7)*33;
#pragma unroll
    for (int a = 0; a < 16; a++)
        gb[w][kp][pbase + 2*a] = v[a];
    __syncwarp();

    float f[24];
    const float TH = 1.0f / 3.0f;
    const float SQ3 = 1.7320508075688772f;
#pragma unroll
    for (int j = 0; j < 8; j++) {
        float2 g0 = gb[w][0][ln + 33*j];
        float2 g1 = gb[w][1][ln + 33*j];
        float r = g0.x;
        f[3*j+0] = (r + 2.f*g1.x) * TH;
        f[3*j+1] = (r - g1.x - SQ3*g1.y) * TH;
        f[3*j+2] = (r - g1.x + SQ3*g1.y) * TH;
    }
    float4* op = (float4*)(out + ((size_t)bco*T_ + t0 + w)*768 + 24*ln);
#pragma unroll
    for (int q = 0; q < 6; q++)
        op[q] = make_float4(f[4*q], f[4*q+1], f[4*q+2], f[4*q+3]);
}

extern "C" void kernel_launch(void* const* d_in, const int* in_sizes, int n_in,
                              void* d_out, int out_size) {
    const float* x   = (const float*)d_in[0];
    const float* w1r = (const float*)d_in[1];
    const float* w1i = (const float*)d_in[2];
    const float* w2r = (const float*)d_in[3];
    const float* w2i = (const float*)d_in[4];
    float* out = (float*)d_out;

    k_fwd_px<<<4096, 256>>>(x);
    k_fwd_t <<<512, 128>>>();
    k_einsum<<<1024, 256>>>(w1r, w1i, w2r, w2i);
    k_inv_t <<<512, 128>>>();
    k_inv_xp<<<4096, 256>>>(out);
}